// round 14
// baseline (speedup 1.0000x reference)
#include <cuda_runtime.h>
#include <cuda_bf16.h>
#include <cstdint>

#define MAXN 100000
#define MAXE 1600000

// Scratch
__device__ float g_h1[MAXN * 128];
__device__ float g_out1[MAXN * 128];
__device__ float g_h2[MAXN * 64];
__device__ float g_dinv[MAXN];
__device__ int   g_deg[MAXN];
__device__ int   g_off[MAXN + 1];
__device__ int   g_cur[MAXN];
__device__ int   g_blk[256];
__device__ int   g_csr[MAXE];          // source node per CSR slot
__device__ float g_csn[MAXE];          // dinv[source] per CSR slot
// Pre-split, pre-transposed weights: Bt[n][k] packed bf16 (hi and lo of residual)
__device__ __nv_bfloat16 g_w1h[128 * 128];
__device__ __nv_bfloat16 g_w1l[128 * 128];
__device__ __nv_bfloat16 g_w2h[64 * 128];
__device__ __nv_bfloat16 g_w2l[64 * 128];

// ---------------------------------------------------------------------------
// CSR construction
// ---------------------------------------------------------------------------
__global__ void k_hist(const int* __restrict__ dst, int E) {
    int i = blockIdx.x * blockDim.x + threadIdx.x;
    if (i < E) atomicAdd(&g_deg[dst[i]], 1);
}
// scan1 also computes dinv (fused; reads g_deg anyway)
__global__ void k_scan1(int n) {
    __shared__ int sh[1024];
    int t = threadIdx.x, i = blockIdx.x * 1024 + t;
    int v = (i < n) ? g_deg[i] : 0;
    if (i < n) g_dinv[i] = rsqrtf((float)(v + 1));
    sh[t] = v;
    __syncthreads();
    for (int o = 1; o < 1024; o <<= 1) {
        int x = (t >= o) ? sh[t - o] : 0;
        __syncthreads();
        sh[t] += x;
        __syncthreads();
    }
    if (i < n) g_off[i] = sh[t] - v;
    if (t == 1023) g_blk[blockIdx.x] = sh[t];
}
__global__ void k_scan2(int nb) {
    __shared__ int sh[128];
    int t = threadIdx.x;
    int v = (t < nb) ? g_blk[t] : 0;
    sh[t] = v;
    __syncthreads();
    for (int o = 1; o < 128; o <<= 1) {
        int x = (t >= o) ? sh[t - o] : 0;
        __syncthreads();
        sh[t] += x;
        __syncthreads();
    }
    if (t < nb) g_blk[t] = sh[t] - v;
}
__global__ void k_scan3(int n, int E) {
    int i = blockIdx.x * blockDim.x + threadIdx.x;
    if (i < n) {
        int o = g_off[i] + g_blk[i >> 10];
        g_off[i] = o;
        g_cur[i] = o;
    }
    if (i == 0) g_off[n] = E;
}
__global__ void k_fill(const int* __restrict__ src, const int* __restrict__ dst, int E) {
    int i = blockIdx.x * blockDim.x + threadIdx.x;
    if (i < E) {
        int s = src[i], d = dst[i];
        int pos = atomicAdd(&g_cur[d], 1);
        g_csr[pos] = s;
        g_csn[pos] = g_dinv[s];
    }
}

// ---------------------------------------------------------------------------
// Weight prep: split fp32 -> bf16 hi + bf16(residual), transposed Bt[n][k].
// ---------------------------------------------------------------------------
__global__ void k_prep_w(const float* __restrict__ W1, const float* __restrict__ W2) {
    int i = blockIdx.x * blockDim.x + threadIdx.x;
    if (i < 128 * 128) {
        int k = i >> 7, nn = i & 127;
        float v = W1[i];
        __nv_bfloat16 h = __float2bfloat16(v);
        __nv_bfloat16 l = __float2bfloat16(v - __bfloat162float(h));
        g_w1h[nn * 128 + k] = h;
        g_w1l[nn * 128 + k] = l;
    } else if (i < 128 * 128 + 128 * 64) {
        int j = i - 128 * 128;
        int k = j >> 6, nn = j & 63;
        float v = W2[j];
        __nv_bfloat16 h = __float2bfloat16(v);
        __nv_bfloat16 l = __float2bfloat16(v - __bfloat162float(h));
        g_w2h[nn * 128 + k] = h;
        g_w2l[nn * 128 + k] = l;
    }
}

// ---------------------------------------------------------------------------
// HMMA GEMM: C[n x NOUT] = A[n x 128] @ W[128 x NOUT]
// bf16 split 3-pass (AhBh + AhBl + AlBh), fp32 accum.
// ---------------------------------------------------------------------------
#define STRIDE_W 68   // words per row: 64 data + 4 pad -> conflict-free fragments

__device__ __forceinline__ void mma_bf16(float* c, const uint32_t* a, const uint32_t* b) {
    asm volatile(
        "mma.sync.aligned.m16n8k16.row.col.f32.bf16.bf16.f32 "
        "{%0,%1,%2,%3}, {%4,%5,%6,%7}, {%8,%9}, {%0,%1,%2,%3};"
        : "+f"(c[0]), "+f"(c[1]), "+f"(c[2]), "+f"(c[3])
        : "r"(a[0]), "r"(a[1]), "r"(a[2]), "r"(a[3]), "r"(b[0]), "r"(b[1]));
}

template <int NOUT>
__global__ void __launch_bounds__(256)
gemm_mma(const float* __restrict__ A, const __nv_bfloat16* __restrict__ Wh,
         const __nv_bfloat16* __restrict__ Wl, float* __restrict__ C, int n) {
    extern __shared__ uint32_t sm[];
    uint32_t* ASH = sm;
    uint32_t* ASL = ASH + 128 * STRIDE_W;
    uint32_t* BSH = ASL + 128 * STRIDE_W;
    uint32_t* BSL = BSH + NOUT * STRIDE_W;

    const int t = threadIdx.x;
    const int wid = t >> 5, lane = t & 31;
    const int g = lane >> 2, tq = lane & 3;
    const int row0 = blockIdx.x * 128;

    for (int i = t; i < NOUT * 64; i += 256) {
        int r = i >> 6, w = i & 63;
        BSH[r * STRIDE_W + w] = ((const uint32_t*)Wh)[i];
        BSL[r * STRIDE_W + w] = ((const uint32_t*)Wl)[i];
    }
    for (int i = t; i < 128 * 64; i += 256) {
        int r = i >> 6, w = i & 63;
        int gr = row0 + r;
        float2 v = make_float2(0.f, 0.f);
        if (gr < n) v = ((const float2*)(A + (size_t)gr * 128))[w];
        __nv_bfloat16 hx = __float2bfloat16(v.x), hy = __float2bfloat16(v.y);
        __nv_bfloat16 lx = __float2bfloat16(v.x - __bfloat162float(hx));
        __nv_bfloat16 ly = __float2bfloat16(v.y - __bfloat162float(hy));
        uint32_t hw = ((uint32_t)__bfloat16_as_ushort(hy) << 16) | __bfloat16_as_ushort(hx);
        uint32_t lw = ((uint32_t)__bfloat16_as_ushort(ly) << 16) | __bfloat16_as_ushort(lx);
        ASH[r * STRIDE_W + w] = hw;
        ASL[r * STRIDE_W + w] = lw;
    }
    __syncthreads();

    constexpr int NT = NOUT / 8;
    float acc[NT][4];
#pragma unroll
    for (int i = 0; i < NT; i++)
#pragma unroll
        for (int j = 0; j < 4; j++) acc[i][j] = 0.f;

    const int wrow = wid * 16;

#pragma unroll
    for (int kk = 0; kk < 8; kk++) {
        uint32_t ah[4], al[4];
        int ra = (wrow + g) * STRIDE_W + kk * 8 + tq;
        int rb = (wrow + g + 8) * STRIDE_W + kk * 8 + tq;
        ah[0] = ASH[ra];     ah[1] = ASH[rb];
        ah[2] = ASH[ra + 4]; ah[3] = ASH[rb + 4];
        al[0] = ASL[ra];     al[1] = ASL[rb];
        al[2] = ASL[ra + 4]; al[3] = ASL[rb + 4];

#pragma unroll
        for (int nt = 0; nt < NT; nt++) {
            int nb = (nt * 8 + g) * STRIDE_W + kk * 8 + tq;
            uint32_t bh[2], bl[2];
            bh[0] = BSH[nb]; bh[1] = BSH[nb + 4];
            bl[0] = BSL[nb]; bl[1] = BSL[nb + 4];
            mma_bf16(acc[nt], ah, bh);
            mma_bf16(acc[nt], ah, bl);
            mma_bf16(acc[nt], al, bh);
        }
    }

    int gr0 = row0 + wrow + g;
    int gr1 = gr0 + 8;
#pragma unroll
    for (int nt = 0; nt < NT; nt++) {
        int col = nt * 8 + tq * 2;
        if (gr0 < n)
            *(float2*)(C + (size_t)gr0 * NOUT + col) = make_float2(acc[nt][0], acc[nt][1]);
        if (gr1 < n)
            *(float2*)(C + (size_t)gr1 * NOUT + col) = make_float2(acc[nt][2], acc[nt][3]);
    }
}

// ---------------------------------------------------------------------------
// Layer-1 gather: warp per destination node, 128 feats, 4-wide edge groups
// with one-group index/weight lookahead to break the idx->row chain.
// ---------------------------------------------------------------------------
__global__ void k_gather128(const float* __restrict__ h, const float* __restrict__ b1,
                            float* __restrict__ out, int n) {
    int node = blockIdx.x * 8 + (threadIdx.x >> 5);
    int lane = threadIdx.x & 31;
    if (node >= n) return;

    float dd = g_dinv[node];
    float self = dd * dd;
    float4 acc0 = ((const float4*)(h + (size_t)node * 128))[lane];
    acc0.x *= self; acc0.y *= self; acc0.z *= self; acc0.w *= self;
    float4 acc1 = make_float4(0.f, 0.f, 0.f, 0.f);

    int e = g_off[node];
    const int end = g_off[node + 1];
    const int stop = e + ((end - e) & ~3);      // last full group boundary

    if (e < stop) {
        // lookahead buffers (group i+1), current group regs
        int pa0 = g_csr[e],     pa1 = g_csr[e + 1];
        int pa2 = g_csr[e + 2], pa3 = g_csr[e + 3];
        float pb0 = g_csn[e],     pb1 = g_csn[e + 1];
        float pb2 = g_csn[e + 2], pb3 = g_csn[e + 3];

        for (; e + 4 < stop; e += 4) {
            int s0 = pa0, s1 = pa1, s2 = pa2, s3 = pa3;
            float w0 = pb0 * dd, w1 = pb1 * dd, w2 = pb2 * dd, w3 = pb3 * dd;
            // issue next group's index/weight loads before consuming rows
            pa0 = g_csr[e + 4]; pa1 = g_csr[e + 5];
            pa2 = g_csr[e + 6]; pa3 = g_csr[e + 7];
            pb0 = g_csn[e + 4]; pb1 = g_csn[e + 5];
            pb2 = g_csn[e + 6]; pb3 = g_csn[e + 7];
            float4 v0 = ((const float4*)(h + (size_t)s0 * 128))[lane];
            float4 v1 = ((const float4*)(h + (size_t)s1 * 128))[lane];
            float4 v2 = ((const float4*)(h + (size_t)s2 * 128))[lane];
            float4 v3 = ((const float4*)(h + (size_t)s3 * 128))[lane];
            acc0.x += v0.x * w0; acc0.y += v0.y * w0; acc0.z += v0.z * w0; acc0.w += v0.w * w0;
            acc1.x += v1.x * w1; acc1.y += v1.y * w1; acc1.z += v1.z * w1; acc1.w += v1.w * w1;
            acc0.x += v2.x * w2; acc0.y += v2.y * w2; acc0.z += v2.z * w2; acc0.w += v2.w * w2;
            acc1.x += v3.x * w3; acc1.y += v3.y * w3; acc1.z += v3.z * w3; acc1.w += v3.w * w3;
        }
        // final full group (already loaded)
        {
            float w0 = pb0 * dd, w1 = pb1 * dd, w2 = pb2 * dd, w3 = pb3 * dd;
            float4 v0 = ((const float4*)(h + (size_t)pa0 * 128))[lane];
            float4 v1 = ((const float4*)(h + (size_t)pa1 * 128))[lane];
            float4 v2 = ((const float4*)(h + (size_t)pa2 * 128))[lane];
            float4 v3 = ((const float4*)(h + (size_t)pa3 * 128))[lane];
            acc0.x += v0.x * w0; acc0.y += v0.y * w0; acc0.z += v0.z * w0; acc0.w += v0.w * w0;
            acc1.x += v1.x * w1; acc1.y += v1.y * w1; acc1.z += v1.z * w1; acc1.w += v1.w * w1;
            acc0.x += v2.x * w2; acc0.y += v2.y * w2; acc0.z += v2.z * w2; acc0.w += v2.w * w2;
            acc1.x += v3.x * w3; acc1.y += v3.y * w3; acc1.z += v3.z * w3; acc1.w += v3.w * w3;
        }
        e = stop;
    }
    for (; e < end; ++e) {
        int s = g_csr[e];
        float w = g_csn[e] * dd;
        float4 v = ((const float4*)(h + (size_t)s * 128))[lane];
        acc0.x += v.x * w; acc0.y += v.y * w; acc0.z += v.z * w; acc0.w += v.w * w;
    }

    float4 bb = ((const float4*)b1)[lane];
    acc0.x = fmaxf(acc0.x + acc1.x + bb.x, 0.f);
    acc0.y = fmaxf(acc0.y + acc1.y + bb.y, 0.f);
    acc0.z = fmaxf(acc0.z + acc1.z + bb.z, 0.f);
    acc0.w = fmaxf(acc0.w + acc1.w + bb.w, 0.f);
    ((float4*)(out + (size_t)node * 128))[lane] = acc0;
}

// ---------------------------------------------------------------------------
// Layer-2 gather + bias + log_softmax: half-warp per node, 4-wide lookahead.
// ---------------------------------------------------------------------------
__global__ void k_gather64_lsm(const float* __restrict__ h, const float* __restrict__ b2,
                               float* __restrict__ out, int n) {
    int node = blockIdx.x * 16 + (threadIdx.x >> 4);
    int lane = threadIdx.x & 15;
    if (node >= n) return;

    float dd = g_dinv[node];
    float self = dd * dd;
    float4 acc0 = ((const float4*)(h + (size_t)node * 64))[lane];
    acc0.x *= self; acc0.y *= self; acc0.z *= self; acc0.w *= self;
    float4 acc1 = make_float4(0.f, 0.f, 0.f, 0.f);

    int e = g_off[node];
    const int end = g_off[node + 1];
    const int stop = e + ((end - e) & ~3);

    if (e < stop) {
        int pa0 = g_csr[e],     pa1 = g_csr[e + 1];
        int pa2 = g_csr[e + 2], pa3 = g_csr[e + 3];
        float pb0 = g_csn[e],     pb1 = g_csn[e + 1];
        float pb2 = g_csn[e + 2], pb3 = g_csn[e + 3];

        for (; e + 4 < stop; e += 4) {
            int s0 = pa0, s1 = pa1, s2 = pa2, s3 = pa3;
            float w0 = pb0 * dd, w1 = pb1 * dd, w2 = pb2 * dd, w3 = pb3 * dd;
            pa0 = g_csr[e + 4]; pa1 = g_csr[e + 5];
            pa2 = g_csr[e + 6]; pa3 = g_csr[e + 7];
            pb0 = g_csn[e + 4]; pb1 = g_csn[e + 5];
            pb2 = g_csn[e + 6]; pb3 = g_csn[e + 7];
            float4 v0 = ((const float4*)(h + (size_t)s0 * 64))[lane];
            float4 v1 = ((const float4*)(h + (size_t)s1 * 64))[lane];
            float4 v2 = ((const float4*)(h + (size_t)s2 * 64))[lane];
            float4 v3 = ((const float4*)(h + (size_t)s3 * 64))[lane];
            acc0.x += v0.x * w0; acc0.y += v0.y * w0; acc0.z += v0.z * w0; acc0.w += v0.w * w0;
            acc1.x += v1.x * w1; acc1.y += v1.y * w1; acc1.z += v1.z * w1; acc1.w += v1.w * w1;
            acc0.x += v2.x * w2; acc0.y += v2.y * w2; acc0.z += v2.z * w2; acc0.w += v2.w * w2;
            acc1.x += v3.x * w3; acc1.y += v3.y * w3; acc1.z += v3.z * w3; acc1.w += v3.w * w3;
        }
        {
            float w0 = pb0 * dd, w1 = pb1 * dd, w2 = pb2 * dd, w3 = pb3 * dd;
            float4 v0 = ((const float4*)(h + (size_t)pa0 * 64))[lane];
            float4 v1 = ((const float4*)(h + (size_t)pa1 * 64))[lane];
            float4 v2 = ((const float4*)(h + (size_t)pa2 * 64))[lane];
            float4 v3 = ((const float4*)(h + (size_t)pa3 * 64))[lane];
            acc0.x += v0.x * w0; acc0.y += v0.y * w0; acc0.z += v0.z * w0; acc0.w += v0.w * w0;
            acc1.x += v1.x * w1; acc1.y += v1.y * w1; acc1.z += v1.z * w1; acc1.w += v1.w * w1;
            acc0.x += v2.x * w2; acc0.y += v2.y * w2; acc0.z += v2.z * w2; acc0.w += v2.w * w2;
            acc1.x += v3.x * w3; acc1.y += v3.y * w3; acc1.z += v3.z * w3; acc1.w += v3.w * w3;
        }
        e = stop;
    }
    for (; e < end; ++e) {
        int s = g_csr[e];
        float w = g_csn[e] * dd;
        float4 v = ((const float4*)(h + (size_t)s * 64))[lane];
        acc0.x += v.x * w; acc0.y += v.y * w; acc0.z += v.z * w; acc0.w += v.w * w;
    }

    float4 bb = ((const float4*)b2)[lane];
    acc0.x += acc1.x + bb.x; acc0.y += acc1.y + bb.y;
    acc0.z += acc1.z + bb.z; acc0.w += acc1.w + bb.w;

    float m = fmaxf(fmaxf(acc0.x, acc0.y), fmaxf(acc0.z, acc0.w));
#pragma unroll
    for (int o = 8; o; o >>= 1) m = fmaxf(m, __shfl_xor_sync(0xFFFFFFFFu, m, o));
    float sum = __expf(acc0.x - m) + __expf(acc0.y - m) + __expf(acc0.z - m) + __expf(acc0.w - m);
#pragma unroll
    for (int o = 8; o; o >>= 1) sum += __shfl_xor_sync(0xFFFFFFFFu, sum, o);
    float lse = __logf(sum) + m;

    // final output: never re-read -> evict-first store
    __stcs((float4*)(out + (size_t)node * 64) + lane,
           make_float4(acc0.x - lse, acc0.y - lse, acc0.z - lse, acc0.w - lse));
}

// ---------------------------------------------------------------------------
extern "C" void kernel_launch(void* const* d_in, const int* in_sizes, int n_in,
                              void* d_out, int out_size) {
    const float* x  = (const float*)d_in[0];
    const float* W1 = (const float*)d_in[1];
    const float* b1 = (const float*)d_in[2];
    const float* W2 = (const float*)d_in[3];
    const float* b2 = (const float*)d_in[4];
    const int*   ei = (const int*)d_in[5];

    const int n = in_sizes[0] / 128;
    const int E = in_sizes[5] / 2;
    const int* src = ei;
    const int* dst = ei + E;
    float* out = (float*)d_out;

    float* h1   = nullptr; cudaGetSymbolAddress((void**)&h1, g_h1);
    float* out1 = nullptr; cudaGetSymbolAddress((void**)&out1, g_out1);
    float* h2   = nullptr; cudaGetSymbolAddress((void**)&h2, g_h2);
    int*   degp = nullptr; cudaGetSymbolAddress((void**)&degp, g_deg);
    __nv_bfloat16 *w1h, *w1l, *w2h, *w2l;
    cudaGetSymbolAddress((void**)&w1h, g_w1h);
    cudaGetSymbolAddress((void**)&w1l, g_w1l);
    cudaGetSymbolAddress((void**)&w2h, g_w2h);
    cudaGetSymbolAddress((void**)&w2l, g_w2l);

    const int T = 256;
    const int nb = (n + 1023) / 1024;

    constexpr int SM1 = (2 * 128 * STRIDE_W + 2 * 128 * STRIDE_W) * 4;
    constexpr int SM2 = (2 * 128 * STRIDE_W + 2 * 64 * STRIDE_W) * 4;
    cudaFuncSetAttribute(gemm_mma<128>, cudaFuncAttributeMaxDynamicSharedMemorySize, SM1);
    cudaFuncSetAttribute(gemm_mma<64>,  cudaFuncAttributeMaxDynamicSharedMemorySize, SM2);

    // One-time stream/event creation (host-side resources only)
    static cudaStream_t s2 = nullptr;
    static cudaEvent_t evFork = nullptr, evJoin = nullptr;
    if (!s2) {
        cudaStreamCreateWithFlags(&s2, cudaStreamNonBlocking);
        cudaEventCreateWithFlags(&evFork, cudaEventDisableTiming);
        cudaEventCreateWithFlags(&evJoin, cudaEventDisableTiming);
    }

    // Fork: GEMM1 path (prep_w -> gemm1) runs on s2, concurrent with CSR build
    cudaEventRecord(evFork, 0);
    cudaStreamWaitEvent(s2, evFork, 0);

    // s2: weight prep + layer-1 GEMM (depends only on x, W1, W2)
    k_prep_w<<<(128 * 128 + 128 * 64 + T - 1) / T, T, 0, s2>>>(W1, W2);
    const int gb = (n + 127) / 128;
    gemm_mma<128><<<gb, T, SM1, s2>>>(x, w1h, w1l, h1, n);
    cudaEventRecord(evJoin, s2);

    // main stream: CSR build (dinv fused into scan1)
    cudaMemsetAsync(degp, 0, n * sizeof(int));
    k_hist<<<(E + T - 1) / T, T>>>(dst, E);
    k_scan1<<<nb, 1024>>>(n);
    k_scan2<<<1, 128>>>(nb);
    k_scan3<<<(n + T - 1) / T, T>>>(n, E);
    k_fill<<<(E + T - 1) / T, T>>>(src, dst, E);

    // Join: gather needs both CSR and gemm1 output
    cudaStreamWaitEvent(0, evJoin, 0);

    k_gather128<<<(n + 7) / 8, T>>>(h1, b1, out1, n);
    gemm_mma<64><<<gb, T, SM2>>>(out1, w2h, w2l, h2, n);
    k_gather64_lsm<<<(n + 15) / 16, T>>>(h2, b2, out, n);
}

// round 15
// speedup vs baseline: 1.0705x; 1.0705x over previous
#include <cuda_runtime.h>
#include <cuda_bf16.h>
#include <cstdint>

#define MAXN 100000
#define MAXE 1600000

// Scratch
__device__ float g_h1[MAXN * 128];
__device__ float g_out1[MAXN * 128];
__device__ float g_h2[MAXN * 64];
__device__ float g_dinv[MAXN];
__device__ int   g_deg[MAXN];
__device__ int   g_off[MAXN + 1];
__device__ int   g_cur[MAXN];
__device__ int   g_blk[256];
__device__ int   g_csr[MAXE];          // source node per CSR slot
__device__ float g_csn[MAXE];          // dinv[source] per CSR slot
// Pre-split, pre-transposed weights: Bt[n][k] packed bf16 (hi and lo of residual)
__device__ __nv_bfloat16 g_w1h[128 * 128];
__device__ __nv_bfloat16 g_w1l[128 * 128];
__device__ __nv_bfloat16 g_w2h[64 * 128];
__device__ __nv_bfloat16 g_w2l[64 * 128];

// ---------------------------------------------------------------------------
// CSR construction
// ---------------------------------------------------------------------------
__global__ void k_hist(const int* __restrict__ dst, int E) {
    int i = blockIdx.x * blockDim.x + threadIdx.x;
    if (i < E) atomicAdd(&g_deg[dst[i]], 1);
}
__global__ void k_dinv(int n) {
    int i = blockIdx.x * blockDim.x + threadIdx.x;
    if (i < n) g_dinv[i] = rsqrtf((float)(g_deg[i] + 1));
}
__global__ void k_scan1(int n) {
    __shared__ int sh[1024];
    int t = threadIdx.x, i = blockIdx.x * 1024 + t;
    int v = (i < n) ? g_deg[i] : 0;
    sh[t] = v;
    __syncthreads();
    for (int o = 1; o < 1024; o <<= 1) {
        int x = (t >= o) ? sh[t - o] : 0;
        __syncthreads();
        sh[t] += x;
        __syncthreads();
    }
    if (i < n) g_off[i] = sh[t] - v;
    if (t == 1023) g_blk[blockIdx.x] = sh[t];
}
__global__ void k_scan2(int nb) {
    __shared__ int sh[128];
    int t = threadIdx.x;
    int v = (t < nb) ? g_blk[t] : 0;
    sh[t] = v;
    __syncthreads();
    for (int o = 1; o < 128; o <<= 1) {
        int x = (t >= o) ? sh[t - o] : 0;
        __syncthreads();
        sh[t] += x;
        __syncthreads();
    }
    if (t < nb) g_blk[t] = sh[t] - v;
}
__global__ void k_scan3(int n, int E) {
    int i = blockIdx.x * blockDim.x + threadIdx.x;
    if (i < n) {
        int o = g_off[i] + g_blk[i >> 10];
        g_off[i] = o;
        g_cur[i] = o;
    }
    if (i == 0) g_off[n] = E;
}
__global__ void k_fill(const int* __restrict__ src, const int* __restrict__ dst, int E) {
    int i = blockIdx.x * blockDim.x + threadIdx.x;
    if (i < E) {
        int s = src[i], d = dst[i];
        int pos = atomicAdd(&g_cur[d], 1);
        g_csr[pos] = s;
        g_csn[pos] = g_dinv[s];
    }
}

// ---------------------------------------------------------------------------
// Weight prep: split fp32 -> bf16 hi + bf16(residual), transposed Bt[n][k].
// ---------------------------------------------------------------------------
__global__ void k_prep_w(const float* __restrict__ W1, const float* __restrict__ W2) {
    int i = blockIdx.x * blockDim.x + threadIdx.x;
    if (i < 128 * 128) {
        int k = i >> 7, nn = i & 127;
        float v = W1[i];
        __nv_bfloat16 h = __float2bfloat16(v);
        __nv_bfloat16 l = __float2bfloat16(v - __bfloat162float(h));
        g_w1h[nn * 128 + k] = h;
        g_w1l[nn * 128 + k] = l;
    } else if (i < 128 * 128 + 128 * 64) {
        int j = i - 128 * 128;
        int k = j >> 6, nn = j & 63;
        float v = W2[j];
        __nv_bfloat16 h = __float2bfloat16(v);
        __nv_bfloat16 l = __float2bfloat16(v - __bfloat162float(h));
        g_w2h[nn * 128 + k] = h;
        g_w2l[nn * 128 + k] = l;
    }
}

// ---------------------------------------------------------------------------
// HMMA GEMM: C[n x NOUT] = A[n x 128] @ W[128 x NOUT]
// bf16 split 3-pass (AhBh + AhBl + AlBh), fp32 accum.
// ---------------------------------------------------------------------------
#define STRIDE_W 68   // words per row: 64 data + 4 pad -> conflict-free fragments

__device__ __forceinline__ void mma_bf16(float* c, const uint32_t* a, const uint32_t* b) {
    asm volatile(
        "mma.sync.aligned.m16n8k16.row.col.f32.bf16.bf16.f32 "
        "{%0,%1,%2,%3}, {%4,%5,%6,%7}, {%8,%9}, {%0,%1,%2,%3};"
        : "+f"(c[0]), "+f"(c[1]), "+f"(c[2]), "+f"(c[3])
        : "r"(a[0]), "r"(a[1]), "r"(a[2]), "r"(a[3]), "r"(b[0]), "r"(b[1]));
}

template <int NOUT>
__global__ void __launch_bounds__(256)
gemm_mma(const float* __restrict__ A, const __nv_bfloat16* __restrict__ Wh,
         const __nv_bfloat16* __restrict__ Wl, float* __restrict__ C, int n) {
    extern __shared__ uint32_t sm[];
    uint32_t* ASH = sm;
    uint32_t* ASL = ASH + 128 * STRIDE_W;
    uint32_t* BSH = ASL + 128 * STRIDE_W;
    uint32_t* BSL = BSH + NOUT * STRIDE_W;

    const int t = threadIdx.x;
    const int wid = t >> 5, lane = t & 31;
    const int g = lane >> 2, tq = lane & 3;
    const int row0 = blockIdx.x * 128;

    for (int i = t; i < NOUT * 64; i += 256) {
        int r = i >> 6, w = i & 63;
        BSH[r * STRIDE_W + w] = ((const uint32_t*)Wh)[i];
        BSL[r * STRIDE_W + w] = ((const uint32_t*)Wl)[i];
    }
    for (int i = t; i < 128 * 64; i += 256) {
        int r = i >> 6, w = i & 63;
        int gr = row0 + r;
        float2 v = make_float2(0.f, 0.f);
        if (gr < n) v = ((const float2*)(A + (size_t)gr * 128))[w];
        __nv_bfloat16 hx = __float2bfloat16(v.x), hy = __float2bfloat16(v.y);
        __nv_bfloat16 lx = __float2bfloat16(v.x - __bfloat162float(hx));
        __nv_bfloat16 ly = __float2bfloat16(v.y - __bfloat162float(hy));
        uint32_t hw = ((uint32_t)__bfloat16_as_ushort(hy) << 16) | __bfloat16_as_ushort(hx);
        uint32_t lw = ((uint32_t)__bfloat16_as_ushort(ly) << 16) | __bfloat16_as_ushort(lx);
        ASH[r * STRIDE_W + w] = hw;
        ASL[r * STRIDE_W + w] = lw;
    }
    __syncthreads();

    constexpr int NT = NOUT / 8;
    float acc[NT][4];
#pragma unroll
    for (int i = 0; i < NT; i++)
#pragma unroll
        for (int j = 0; j < 4; j++) acc[i][j] = 0.f;

    const int wrow = wid * 16;

#pragma unroll
    for (int kk = 0; kk < 8; kk++) {
        uint32_t ah[4], al[4];
        int ra = (wrow + g) * STRIDE_W + kk * 8 + tq;
        int rb = (wrow + g + 8) * STRIDE_W + kk * 8 + tq;
        ah[0] = ASH[ra];     ah[1] = ASH[rb];
        ah[2] = ASH[ra + 4]; ah[3] = ASH[rb + 4];
        al[0] = ASL[ra];     al[1] = ASL[rb];
        al[2] = ASL[ra + 4]; al[3] = ASL[rb + 4];

#pragma unroll
        for (int nt = 0; nt < NT; nt++) {
            int nb = (nt * 8 + g) * STRIDE_W + kk * 8 + tq;
            uint32_t bh[2], bl[2];
            bh[0] = BSH[nb]; bh[1] = BSH[nb + 4];
            bl[0] = BSL[nb]; bl[1] = BSL[nb + 4];
            mma_bf16(acc[nt], ah, bh);
            mma_bf16(acc[nt], ah, bl);
            mma_bf16(acc[nt], al, bh);
        }
    }

    int gr0 = row0 + wrow + g;
    int gr1 = gr0 + 8;
#pragma unroll
    for (int nt = 0; nt < NT; nt++) {
        int col = nt * 8 + tq * 2;
        if (gr0 < n)
            *(float2*)(C + (size_t)gr0 * NOUT + col) = make_float2(acc[nt][0], acc[nt][1]);
        if (gr1 < n)
            *(float2*)(C + (size_t)gr1 * NOUT + col) = make_float2(acc[nt][2], acc[nt][3]);
    }
}

// ---------------------------------------------------------------------------
// Layer-1 gather: warp per destination node, 128 feats, 4-wide edge unroll.
// Operates on node range [start, start+count).
// ---------------------------------------------------------------------------
__global__ void k_gather128(const float* __restrict__ h, const float* __restrict__ b1,
                            float* __restrict__ out, int start, int count, int n) {
    int node = start + blockIdx.x * 8 + (threadIdx.x >> 5);
    int lane = threadIdx.x & 31;
    if (node >= start + count || node >= n) return;

    float dd = g_dinv[node];
    float self = dd * dd;
    float4 acc0 = ((const float4*)(h + (size_t)node * 128))[lane];
    acc0.x *= self; acc0.y *= self; acc0.z *= self; acc0.w *= self;
    float4 acc1 = make_float4(0.f, 0.f, 0.f, 0.f);

    int e = g_off[node];
    const int end = g_off[node + 1];

    for (; e + 3 < end; e += 4) {
        int s0 = g_csr[e],     s1 = g_csr[e + 1];
        int s2 = g_csr[e + 2], s3 = g_csr[e + 3];
        float w0 = g_csn[e] * dd,     w1 = g_csn[e + 1] * dd;
        float w2 = g_csn[e + 2] * dd, w3 = g_csn[e + 3] * dd;
        float4 v0 = ((const float4*)(h + (size_t)s0 * 128))[lane];
        float4 v1 = ((const float4*)(h + (size_t)s1 * 128))[lane];
        float4 v2 = ((const float4*)(h + (size_t)s2 * 128))[lane];
        float4 v3 = ((const float4*)(h + (size_t)s3 * 128))[lane];
        acc0.x += v0.x * w0; acc0.y += v0.y * w0; acc0.z += v0.z * w0; acc0.w += v0.w * w0;
        acc1.x += v1.x * w1; acc1.y += v1.y * w1; acc1.z += v1.z * w1; acc1.w += v1.w * w1;
        acc0.x += v2.x * w2; acc0.y += v2.y * w2; acc0.z += v2.z * w2; acc0.w += v2.w * w2;
        acc1.x += v3.x * w3; acc1.y += v3.y * w3; acc1.z += v3.z * w3; acc1.w += v3.w * w3;
    }
    for (; e < end; ++e) {
        int s = g_csr[e];
        float w = g_csn[e] * dd;
        float4 v = ((const float4*)(h + (size_t)s * 128))[lane];
        acc0.x += v.x * w; acc0.y += v.y * w; acc0.z += v.z * w; acc0.w += v.w * w;
    }

    float4 bb = ((const float4*)b1)[lane];
    acc0.x = fmaxf(acc0.x + acc1.x + bb.x, 0.f);
    acc0.y = fmaxf(acc0.y + acc1.y + bb.y, 0.f);
    acc0.z = fmaxf(acc0.z + acc1.z + bb.z, 0.f);
    acc0.w = fmaxf(acc0.w + acc1.w + bb.w, 0.f);
    ((float4*)(out + (size_t)node * 128))[lane] = acc0;
}

// ---------------------------------------------------------------------------
// Layer-2 gather + bias + log_softmax: half-warp per node, 4-wide unroll.
// ---------------------------------------------------------------------------
__global__ void k_gather64_lsm(const float* __restrict__ h, const float* __restrict__ b2,
                               float* __restrict__ out, int n) {
    int node = blockIdx.x * 16 + (threadIdx.x >> 4);
    int lane = threadIdx.x & 15;
    if (node >= n) return;

    float dd = g_dinv[node];
    float self = dd * dd;
    float4 acc0 = ((const float4*)(h + (size_t)node * 64))[lane];
    acc0.x *= self; acc0.y *= self; acc0.z *= self; acc0.w *= self;
    float4 acc1 = make_float4(0.f, 0.f, 0.f, 0.f);

    int e = g_off[node];
    const int end = g_off[node + 1];

    for (; e + 3 < end; e += 4) {
        int s0 = g_csr[e],     s1 = g_csr[e + 1];
        int s2 = g_csr[e + 2], s3 = g_csr[e + 3];
        float w0 = g_csn[e] * dd,     w1 = g_csn[e + 1] * dd;
        float w2 = g_csn[e + 2] * dd, w3 = g_csn[e + 3] * dd;
        float4 v0 = ((const float4*)(h + (size_t)s0 * 64))[lane];
        float4 v1 = ((const float4*)(h + (size_t)s1 * 64))[lane];
        float4 v2 = ((const float4*)(h + (size_t)s2 * 64))[lane];
        float4 v3 = ((const float4*)(h + (size_t)s3 * 64))[lane];
        acc0.x += v0.x * w0; acc0.y += v0.y * w0; acc0.z += v0.z * w0; acc0.w += v0.w * w0;
        acc1.x += v1.x * w1; acc1.y += v1.y * w1; acc1.z += v1.z * w1; acc1.w += v1.w * w1;
        acc0.x += v2.x * w2; acc0.y += v2.y * w2; acc0.z += v2.z * w2; acc0.w += v2.w * w2;
        acc1.x += v3.x * w3; acc1.y += v3.y * w3; acc1.z += v3.z * w3; acc1.w += v3.w * w3;
    }
    for (; e < end; ++e) {
        int s = g_csr[e];
        float w = g_csn[e] * dd;
        float4 v = ((const float4*)(h + (size_t)s * 64))[lane];
        acc0.x += v.x * w; acc0.y += v.y * w; acc0.z += v.z * w; acc0.w += v.w * w;
    }

    float4 bb = ((const float4*)b2)[lane];
    acc0.x += acc1.x + bb.x; acc0.y += acc1.y + bb.y;
    acc0.z += acc1.z + bb.z; acc0.w += acc1.w + bb.w;

    float m = fmaxf(fmaxf(acc0.x, acc0.y), fmaxf(acc0.z, acc0.w));
#pragma unroll
    for (int o = 8; o; o >>= 1) m = fmaxf(m, __shfl_xor_sync(0xFFFFFFFFu, m, o));
    float sum = __expf(acc0.x - m) + __expf(acc0.y - m) + __expf(acc0.z - m) + __expf(acc0.w - m);
#pragma unroll
    for (int o = 8; o; o >>= 1) sum += __shfl_xor_sync(0xFFFFFFFFu, sum, o);
    float lse = __logf(sum) + m;

    ((float4*)(out + (size_t)node * 64))[lane] =
        make_float4(acc0.x - lse, acc0.y - lse, acc0.z - lse, acc0.w - lse);
}

// ---------------------------------------------------------------------------
extern "C" void kernel_launch(void* const* d_in, const int* in_sizes, int n_in,
                              void* d_out, int out_size) {
    const float* x  = (const float*)d_in[0];
    const float* W1 = (const float*)d_in[1];
    const float* b1 = (const float*)d_in[2];
    const float* W2 = (const float*)d_in[3];
    const float* b2 = (const float*)d_in[4];
    const int*   ei = (const int*)d_in[5];

    const int n = in_sizes[0] / 128;
    const int E = in_sizes[5] / 2;
    const int* src = ei;
    const int* dst = ei + E;
    float* out = (float*)d_out;

    float* h1   = nullptr; cudaGetSymbolAddress((void**)&h1, g_h1);
    float* out1 = nullptr; cudaGetSymbolAddress((void**)&out1, g_out1);
    float* h2   = nullptr; cudaGetSymbolAddress((void**)&h2, g_h2);
    int*   degp = nullptr; cudaGetSymbolAddress((void**)&degp, g_deg);
    __nv_bfloat16 *w1h, *w1l, *w2h, *w2l;
    cudaGetSymbolAddress((void**)&w1h, g_w1h);
    cudaGetSymbolAddress((void**)&w1l, g_w1l);
    cudaGetSymbolAddress((void**)&w2h, g_w2h);
    cudaGetSymbolAddress((void**)&w2l, g_w2l);

    const int T = 256;
    const int nb = (n + 1023) / 1024;

    constexpr int SM1 = (2 * 128 * STRIDE_W + 2 * 128 * STRIDE_W) * 4;
    constexpr int SM2 = (2 * 128 * STRIDE_W + 2 * 64 * STRIDE_W) * 4;
    cudaFuncSetAttribute(gemm_mma<128>, cudaFuncAttributeMaxDynamicSharedMemorySize, SM1);
    cudaFuncSetAttribute(gemm_mma<64>,  cudaFuncAttributeMaxDynamicSharedMemorySize, SM2);

    // One-time stream/event creation (host-side resources only)
    static cudaStream_t s2 = nullptr;
    static cudaEvent_t evFork = nullptr, evJoin = nullptr, evGA = nullptr, evG2 = nullptr;
    if (!s2) {
        cudaStreamCreateWithFlags(&s2, cudaStreamNonBlocking);
        cudaEventCreateWithFlags(&evFork, cudaEventDisableTiming);
        cudaEventCreateWithFlags(&evJoin, cudaEventDisableTiming);
        cudaEventCreateWithFlags(&evGA, cudaEventDisableTiming);
        cudaEventCreateWithFlags(&evG2, cudaEventDisableTiming);
    }

    // Fork: GEMM1 path (prep_w -> gemm1) runs on s2, concurrent with CSR build
    cudaEventRecord(evFork, 0);
    cudaStreamWaitEvent(s2, evFork, 0);

    // s2: weight prep + layer-1 GEMM (depends only on x, W1, W2)
    k_prep_w<<<(128 * 128 + 128 * 64 + T - 1) / T, T, 0, s2>>>(W1, W2);
    const int gb = (n + 127) / 128;
    gemm_mma<128><<<gb, T, SM1, s2>>>(x, w1h, w1l, h1, n);
    cudaEventRecord(evJoin, s2);

    // main stream: CSR build
    cudaMemsetAsync(degp, 0, n * sizeof(int));
    k_hist<<<(E + T - 1) / T, T>>>(dst, E);
    k_dinv<<<(n + T - 1) / T, T>>>(n);
    k_scan1<<<nb, 1024>>>(n);
    k_scan2<<<1, 128>>>(nb);
    k_scan3<<<(n + T - 1) / T, T>>>(n, E);
    k_fill<<<(E + T - 1) / T, T>>>(src, dst, E);

    // Join: gather needs both CSR and gemm1 output
    cudaStreamWaitEvent(0, evJoin, 0);

    // Chunked overlap: gather128 chunk A -> (gemm2 chunk A on s2) || gather128 chunk B
    const int nA = ((n / 2 + 127) / 128) * 128;   // chunk A node count (row-tile aligned)
    const int nB = n - nA;

    k_gather128<<<(nA + 7) / 8, T>>>(h1, b1, out1, 0, nA, n);
    cudaEventRecord(evGA, 0);

    // s2: gemm2 on rows [0, nA) while main does gather128 on [nA, n)
    cudaStreamWaitEvent(s2, evGA, 0);
    gemm_mma<64><<<nA / 128, T, SM2, s2>>>(out1, w2h, w2l, h2, nA);
    cudaEventRecord(evG2, s2);

    k_gather128<<<(nB + 7) / 8, T>>>(h1, b1, out1, nA, nB, n);

    // main: gemm2 on rows [nA, n) (depends on chunk B, same stream)
    gemm_mma<64><<<(nB + 127) / 128, T, SM2>>>(out1 + (size_t)nA * 128, w2h, w2l,
                                               h2 + (size_t)nA * 64, nB);

    // gather64 needs ALL of h2 (both chunks)
    cudaStreamWaitEvent(0, evG2, 0);
    k_gather64_lsm<<<(n + 15) / 16, T>>>(h2, b2, out, n);
}

// round 16
// speedup vs baseline: 1.1239x; 1.0499x over previous
#include <cuda_runtime.h>
#include <cuda_bf16.h>
#include <cuda_fp16.h>
#include <cstdint>

#define MAXN 100000
#define MAXE 1600000

// Scratch
__device__ __half g_h1h[MAXN * 128];   // x @ W1, fp16 (gather payload)
__device__ float  g_out1[MAXN * 128];  // relu(aggregate + b1), fp32
__device__ __half g_h2h[MAXN * 64];    // out1 @ W2, fp16 (gather payload)
__device__ float  g_dinv[MAXN];
__device__ int    g_deg[MAXN];
__device__ int    g_off[MAXN + 1];
__device__ int    g_cur[MAXN];
__device__ int    g_blk[256];
__device__ int    g_csr[MAXE];         // source node per CSR slot
__device__ float  g_csn[MAXE];         // dinv[source] per CSR slot
// Pre-split, pre-transposed weights: Bt[n][k] packed bf16 (hi and lo of residual)
__device__ __nv_bfloat16 g_w1h[128 * 128];
__device__ __nv_bfloat16 g_w1l[128 * 128];
__device__ __nv_bfloat16 g_w2h[64 * 128];
__device__ __nv_bfloat16 g_w2l[64 * 128];

// ---------------------------------------------------------------------------
// CSR construction
// ---------------------------------------------------------------------------
__global__ void k_hist(const int* __restrict__ dst, int E) {
    int i = blockIdx.x * blockDim.x + threadIdx.x;
    if (i < E) atomicAdd(&g_deg[dst[i]], 1);
}
__global__ void k_dinv(int n) {
    int i = blockIdx.x * blockDim.x + threadIdx.x;
    if (i < n) g_dinv[i] = rsqrtf((float)(g_deg[i] + 1));
}
__global__ void k_scan1(int n) {
    __shared__ int sh[1024];
    int t = threadIdx.x, i = blockIdx.x * 1024 + t;
    int v = (i < n) ? g_deg[i] : 0;
    sh[t] = v;
    __syncthreads();
    for (int o = 1; o < 1024; o <<= 1) {
        int x = (t >= o) ? sh[t - o] : 0;
        __syncthreads();
        sh[t] += x;
        __syncthreads();
    }
    if (i < n) g_off[i] = sh[t] - v;
    if (t == 1023) g_blk[blockIdx.x] = sh[t];
}
__global__ void k_scan2(int nb) {
    __shared__ int sh[128];
    int t = threadIdx.x;
    int v = (t < nb) ? g_blk[t] : 0;
    sh[t] = v;
    __syncthreads();
    for (int o = 1; o < 128; o <<= 1) {
        int x = (t >= o) ? sh[t - o] : 0;
        __syncthreads();
        sh[t] += x;
        __syncthreads();
    }
    if (t < nb) g_blk[t] = sh[t] - v;
}
__global__ void k_scan3(int n, int E) {
    int i = blockIdx.x * blockDim.x + threadIdx.x;
    if (i < n) {
        int o = g_off[i] + g_blk[i >> 10];
        g_off[i] = o;
        g_cur[i] = o;
    }
    if (i == 0) g_off[n] = E;
}
__global__ void k_fill(const int* __restrict__ src, const int* __restrict__ dst, int E) {
    int i = blockIdx.x * blockDim.x + threadIdx.x;
    if (i < E) {
        int s = src[i], d = dst[i];
        int pos = atomicAdd(&g_cur[d], 1);
        g_csr[pos] = s;
        g_csn[pos] = g_dinv[s];
    }
}

// ---------------------------------------------------------------------------
// Weight prep: split fp32 -> bf16 hi + bf16(residual), transposed Bt[n][k].
// ---------------------------------------------------------------------------
__global__ void k_prep_w(const float* __restrict__ W1, const float* __restrict__ W2) {
    int i = blockIdx.x * blockDim.x + threadIdx.x;
    if (i < 128 * 128) {
        int k = i >> 7, nn = i & 127;
        float v = W1[i];
        __nv_bfloat16 h = __float2bfloat16(v);
        __nv_bfloat16 l = __float2bfloat16(v - __bfloat162float(h));
        g_w1h[nn * 128 + k] = h;
        g_w1l[nn * 128 + k] = l;
    } else if (i < 128 * 128 + 128 * 64) {
        int j = i - 128 * 128;
        int k = j >> 6, nn = j & 63;
        float v = W2[j];
        __nv_bfloat16 h = __float2bfloat16(v);
        __nv_bfloat16 l = __float2bfloat16(v - __bfloat162float(h));
        g_w2h[nn * 128 + k] = h;
        g_w2l[nn * 128 + k] = l;
    }
}

// ---------------------------------------------------------------------------
// HMMA GEMM: C[n x NOUT] = A[n x 128] @ W[128 x NOUT]
// bf16 split 3-pass (AhBh + AhBl + AlBh), fp32 accum, fp16 output.
// ---------------------------------------------------------------------------
#define STRIDE_W 68   // words per row: 64 data + 4 pad -> conflict-free fragments

__device__ __forceinline__ void mma_bf16(float* c, const uint32_t* a, const uint32_t* b) {
    asm volatile(
        "mma.sync.aligned.m16n8k16.row.col.f32.bf16.bf16.f32 "
        "{%0,%1,%2,%3}, {%4,%5,%6,%7}, {%8,%9}, {%0,%1,%2,%3};"
        : "+f"(c[0]), "+f"(c[1]), "+f"(c[2]), "+f"(c[3])
        : "r"(a[0]), "r"(a[1]), "r"(a[2]), "r"(a[3]), "r"(b[0]), "r"(b[1]));
}

template <int NOUT>
__global__ void __launch_bounds__(256)
gemm_mma(const float* __restrict__ A, const __nv_bfloat16* __restrict__ Wh,
         const __nv_bfloat16* __restrict__ Wl, __half* __restrict__ C, int n) {
    extern __shared__ uint32_t sm[];
    uint32_t* ASH = sm;
    uint32_t* ASL = ASH + 128 * STRIDE_W;
    uint32_t* BSH = ASL + 128 * STRIDE_W;
    uint32_t* BSL = BSH + NOUT * STRIDE_W;

    const int t = threadIdx.x;
    const int wid = t >> 5, lane = t & 31;
    const int g = lane >> 2, tq = lane & 3;
    const int row0 = blockIdx.x * 128;

    for (int i = t; i < NOUT * 64; i += 256) {
        int r = i >> 6, w = i & 63;
        BSH[r * STRIDE_W + w] = ((const uint32_t*)Wh)[i];
        BSL[r * STRIDE_W + w] = ((const uint32_t*)Wl)[i];
    }
    for (int i = t; i < 128 * 64; i += 256) {
        int r = i >> 6, w = i & 63;
        int gr = row0 + r;
        float2 v = make_float2(0.f, 0.f);
        if (gr < n) v = ((const float2*)(A + (size_t)gr * 128))[w];
        __nv_bfloat16 hx = __float2bfloat16(v.x), hy = __float2bfloat16(v.y);
        __nv_bfloat16 lx = __float2bfloat16(v.x - __bfloat162float(hx));
        __nv_bfloat16 ly = __float2bfloat16(v.y - __bfloat162float(hy));
        uint32_t hw = ((uint32_t)__bfloat16_as_ushort(hy) << 16) | __bfloat16_as_ushort(hx);
        uint32_t lw = ((uint32_t)__bfloat16_as_ushort(ly) << 16) | __bfloat16_as_ushort(lx);
        ASH[r * STRIDE_W + w] = hw;
        ASL[r * STRIDE_W + w] = lw;
    }
    __syncthreads();

    constexpr int NT = NOUT / 8;
    float acc[NT][4];
#pragma unroll
    for (int i = 0; i < NT; i++)
#pragma unroll
        for (int j = 0; j < 4; j++) acc[i][j] = 0.f;

    const int wrow = wid * 16;

#pragma unroll
    for (int kk = 0; kk < 8; kk++) {
        uint32_t ah[4], al[4];
        int ra = (wrow + g) * STRIDE_W + kk * 8 + tq;
        int rb = (wrow + g + 8) * STRIDE_W + kk * 8 + tq;
        ah[0] = ASH[ra];     ah[1] = ASH[rb];
        ah[2] = ASH[ra + 4]; ah[3] = ASH[rb + 4];
        al[0] = ASL[ra];     al[1] = ASL[rb];
        al[2] = ASL[ra + 4]; al[3] = ASL[rb + 4];

#pragma unroll
        for (int nt = 0; nt < NT; nt++) {
            int nb = (nt * 8 + g) * STRIDE_W + kk * 8 + tq;
            uint32_t bh[2], bl[2];
            bh[0] = BSH[nb]; bh[1] = BSH[nb + 4];
            bl[0] = BSL[nb]; bl[1] = BSL[nb + 4];
            mma_bf16(acc[nt], ah, bh);
            mma_bf16(acc[nt], ah, bl);
            mma_bf16(acc[nt], al, bh);
        }
    }

    int gr0 = row0 + wrow + g;
    int gr1 = gr0 + 8;
#pragma unroll
    for (int nt = 0; nt < NT; nt++) {
        int col = nt * 8 + tq * 2;
        if (gr0 < n)
            *(__half2*)(C + (size_t)gr0 * NOUT + col) = __floats2half2_rn(acc[nt][0], acc[nt][1]);
        if (gr1 < n)
            *(__half2*)(C + (size_t)gr1 * NOUT + col) = __floats2half2_rn(acc[nt][2], acc[nt][3]);
    }
}

// ---------------------------------------------------------------------------
// Layer-1 gather: warp per destination node, 128 fp16 feats (lane = 4),
// fp32 accumulate, 4-wide edge unroll. Node range [start, start+count).
// ---------------------------------------------------------------------------
__device__ __forceinline__ float4 ld_h4(const __half* base, int lane) {
    uint2 raw = ((const uint2*)base)[lane];
    float2 a = __half22float2(*(__half2*)&raw.x);
    float2 b = __half22float2(*(__half2*)&raw.y);
    return make_float4(a.x, a.y, b.x, b.y);
}

__global__ void k_gather128(const __half* __restrict__ h, const float* __restrict__ b1,
                            float* __restrict__ out, int start, int count, int n) {
    int node = start + blockIdx.x * 8 + (threadIdx.x >> 5);
    int lane = threadIdx.x & 31;
    if (node >= start + count || node >= n) return;

    float dd = g_dinv[node];
    float self = dd * dd;
    float4 sv = ld_h4(h + (size_t)node * 128, lane);
    float4 acc0 = make_float4(sv.x * self, sv.y * self, sv.z * self, sv.w * self);
    float4 acc1 = make_float4(0.f, 0.f, 0.f, 0.f);

    int e = g_off[node];
    const int end = g_off[node + 1];

    for (; e + 3 < end; e += 4) {
        int s0 = g_csr[e],     s1 = g_csr[e + 1];
        int s2 = g_csr[e + 2], s3 = g_csr[e + 3];
        float w0 = g_csn[e] * dd,     w1 = g_csn[e + 1] * dd;
        float w2 = g_csn[e + 2] * dd, w3 = g_csn[e + 3] * dd;
        float4 v0 = ld_h4(h + (size_t)s0 * 128, lane);
        float4 v1 = ld_h4(h + (size_t)s1 * 128, lane);
        float4 v2 = ld_h4(h + (size_t)s2 * 128, lane);
        float4 v3 = ld_h4(h + (size_t)s3 * 128, lane);
        acc0.x += v0.x * w0; acc0.y += v0.y * w0; acc0.z += v0.z * w0; acc0.w += v0.w * w0;
        acc1.x += v1.x * w1; acc1.y += v1.y * w1; acc1.z += v1.z * w1; acc1.w += v1.w * w1;
        acc0.x += v2.x * w2; acc0.y += v2.y * w2; acc0.z += v2.z * w2; acc0.w += v2.w * w2;
        acc1.x += v3.x * w3; acc1.y += v3.y * w3; acc1.z += v3.z * w3; acc1.w += v3.w * w3;
    }
    for (; e < end; ++e) {
        int s = g_csr[e];
        float w = g_csn[e] * dd;
        float4 v = ld_h4(h + (size_t)s * 128, lane);
        acc0.x += v.x * w; acc0.y += v.y * w; acc0.z += v.z * w; acc0.w += v.w * w;
    }

    float4 bb = ((const float4*)b1)[lane];
    acc0.x = fmaxf(acc0.x + acc1.x + bb.x, 0.f);
    acc0.y = fmaxf(acc0.y + acc1.y + bb.y, 0.f);
    acc0.z = fmaxf(acc0.z + acc1.z + bb.z, 0.f);
    acc0.w = fmaxf(acc0.w + acc1.w + bb.w, 0.f);
    ((float4*)(out + (size_t)node * 128))[lane] = acc0;
}

// ---------------------------------------------------------------------------
// Layer-2 gather + bias + log_softmax: half-warp per node, 64 fp16 feats.
// ---------------------------------------------------------------------------
__global__ void k_gather64_lsm(const __half* __restrict__ h, const float* __restrict__ b2,
                               float* __restrict__ out, int n) {
    int node = blockIdx.x * 16 + (threadIdx.x >> 4);
    int lane = threadIdx.x & 15;
    if (node >= n) return;

    float dd = g_dinv[node];
    float self = dd * dd;
    float4 sv = ld_h4(h + (size_t)node * 64, lane);
    float4 acc0 = make_float4(sv.x * self, sv.y * self, sv.z * self, sv.w * self);
    float4 acc1 = make_float4(0.f, 0.f, 0.f, 0.f);

    int e = g_off[node];
    const int end = g_off[node + 1];

    for (; e + 3 < end; e += 4) {
        int s0 = g_csr[e],     s1 = g_csr[e + 1];
        int s2 = g_csr[e + 2], s3 = g_csr[e + 3];
        float w0 = g_csn[e] * dd,     w1 = g_csn[e + 1] * dd;
        float w2 = g_csn[e + 2] * dd, w3 = g_csn[e + 3] * dd;
        float4 v0 = ld_h4(h + (size_t)s0 * 64, lane);
        float4 v1 = ld_h4(h + (size_t)s1 * 64, lane);
        float4 v2 = ld_h4(h + (size_t)s2 * 64, lane);
        float4 v3 = ld_h4(h + (size_t)s3 * 64, lane);
        acc0.x += v0.x * w0; acc0.y += v0.y * w0; acc0.z += v0.z * w0; acc0.w += v0.w * w0;
        acc1.x += v1.x * w1; acc1.y += v1.y * w1; acc1.z += v1.z * w1; acc1.w += v1.w * w1;
        acc0.x += v2.x * w2; acc0.y += v2.y * w2; acc0.z += v2.z * w2; acc0.w += v2.w * w2;
        acc1.x += v3.x * w3; acc1.y += v3.y * w3; acc1.z += v3.z * w3; acc1.w += v3.w * w3;
    }
    for (; e < end; ++e) {
        int s = g_csr[e];
        float w = g_csn[e] * dd;
        float4 v = ld_h4(h + (size_t)s * 64, lane);
        acc0.x += v.x * w; acc0.y += v.y * w; acc0.z += v.z * w; acc0.w += v.w * w;
    }

    float4 bb = ((const float4*)b2)[lane];
    acc0.x += acc1.x + bb.x; acc0.y += acc1.y + bb.y;
    acc0.z += acc1.z + bb.z; acc0.w += acc1.w + bb.w;

    float m = fmaxf(fmaxf(acc0.x, acc0.y), fmaxf(acc0.z, acc0.w));
#pragma unroll
    for (int o = 8; o; o >>= 1) m = fmaxf(m, __shfl_xor_sync(0xFFFFFFFFu, m, o));
    float sum = __expf(acc0.x - m) + __expf(acc0.y - m) + __expf(acc0.z - m) + __expf(acc0.w - m);
#pragma unroll
    for (int o = 8; o; o >>= 1) sum += __shfl_xor_sync(0xFFFFFFFFu, sum, o);
    float lse = __logf(sum) + m;

    ((float4*)(out + (size_t)node * 64))[lane] =
        make_float4(acc0.x - lse, acc0.y - lse, acc0.z - lse, acc0.w - lse);
}

// ---------------------------------------------------------------------------
extern "C" void kernel_launch(void* const* d_in, const int* in_sizes, int n_in,
                              void* d_out, int out_size) {
    const float* x  = (const float*)d_in[0];
    const float* W1 = (const float*)d_in[1];
    const float* b1 = (const float*)d_in[2];
    const float* W2 = (const float*)d_in[3];
    const float* b2 = (const float*)d_in[4];
    const int*   ei = (const int*)d_in[5];

    const int n = in_sizes[0] / 128;
    const int E = in_sizes[5] / 2;
    const int* src = ei;
    const int* dst = ei + E;
    float* out = (float*)d_out;

    __half* h1h  = nullptr; cudaGetSymbolAddress((void**)&h1h, g_h1h);
    float*  out1 = nullptr; cudaGetSymbolAddress((void**)&out1, g_out1);
    __half* h2h  = nullptr; cudaGetSymbolAddress((void**)&h2h, g_h2h);
    int*    degp = nullptr; cudaGetSymbolAddress((void**)&degp, g_deg);
    __nv_bfloat16 *w1h, *w1l, *w2h, *w2l;
    cudaGetSymbolAddress((void**)&w1h, g_w1h);
    cudaGetSymbolAddress((void**)&w1l, g_w1l);
    cudaGetSymbolAddress((void**)&w2h, g_w2h);
    cudaGetSymbolAddress((void**)&w2l, g_w2l);

    const int T = 256;
    const int nb = (n + 1023) / 1024;

    constexpr int SM1 = (2 * 128 * STRIDE_W + 2 * 128 * STRIDE_W) * 4;
    constexpr int SM2 = (2 * 128 * STRIDE_W + 2 * 64 * STRIDE_W) * 4;
    cudaFuncSetAttribute(gemm_mma<128>, cudaFuncAttributeMaxDynamicSharedMemorySize, SM1);
    cudaFuncSetAttribute(gemm_mma<64>,  cudaFuncAttributeMaxDynamicSharedMemorySize, SM2);

    // One-time stream/event creation (host-side resources only)
    static cudaStream_t s2 = nullptr;
    static cudaEvent_t evFork = nullptr, evJoin = nullptr, evGA = nullptr, evG2 = nullptr;
    if (!s2) {
        cudaStreamCreateWithFlags(&s2, cudaStreamNonBlocking);
        cudaEventCreateWithFlags(&evFork, cudaEventDisableTiming);
        cudaEventCreateWithFlags(&evJoin, cudaEventDisableTiming);
        cudaEventCreateWithFlags(&evGA, cudaEventDisableTiming);
        cudaEventCreateWithFlags(&evG2, cudaEventDisableTiming);
    }

    // Fork: GEMM1 path (prep_w -> gemm1) runs on s2, concurrent with CSR build
    cudaEventRecord(evFork, 0);
    cudaStreamWaitEvent(s2, evFork, 0);

    // s2: weight prep + layer-1 GEMM (depends only on x, W1, W2)
    k_prep_w<<<(128 * 128 + 128 * 64 + T - 1) / T, T, 0, s2>>>(W1, W2);
    const int gb = (n + 127) / 128;
    gemm_mma<128><<<gb, T, SM1, s2>>>(x, w1h, w1l, h1h, n);
    cudaEventRecord(evJoin, s2);

    // main stream: CSR build
    cudaMemsetAsync(degp, 0, n * sizeof(int));
    k_hist<<<(E + T - 1) / T, T>>>(dst, E);
    k_dinv<<<(n + T - 1) / T, T>>>(n);
    k_scan1<<<nb, 1024>>>(n);
    k_scan2<<<1, 128>>>(nb);
    k_scan3<<<(n + T - 1) / T, T>>>(n, E);
    k_fill<<<(E + T - 1) / T, T>>>(src, dst, E);

    // Join: gather needs both CSR and gemm1 output
    cudaStreamWaitEvent(0, evJoin, 0);

    // Chunked overlap: gather128 chunk A -> (gemm2 chunk A on s2) || gather128 chunk B
    const int nA = ((n / 2 + 127) / 128) * 128;   // chunk A node count (row-tile aligned)
    const int nB = n - nA;

    k_gather128<<<(nA + 7) / 8, T>>>(h1h, b1, out1, 0, nA, n);
    cudaEventRecord(evGA, 0);

    // s2: gemm2 on rows [0, nA) while main does gather128 on [nA, n)
    cudaStreamWaitEvent(s2, evGA, 0);
    gemm_mma<64><<<nA / 128, T, SM2, s2>>>(out1, w2h, w2l, h2h, nA);
    cudaEventRecord(evG2, s2);

    k_gather128<<<(nB + 7) / 8, T>>>(h1h, b1, out1, nA, nB, n);

    // main: gemm2 on rows [nA, n) (depends on chunk B, same stream)
    gemm_mma<64><<<(nB + 127) / 128, T, SM2>>>(out1 + (size_t)nA * 128, w2h, w2l,
                                               h2h + (size_t)nA * 64, nB);

    // gather64 needs ALL of h2 (both chunks)
    cudaStreamWaitEvent(0, evG2, 0);
    k_gather64_lsm<<<(n + 15) / 16, T>>>(h2h, b2, out, n);
}

// round 17
// speedup vs baseline: 1.1527x; 1.0256x over previous
#include <cuda_runtime.h>
#include <cuda_bf16.h>
#include <cuda_fp16.h>
#include <cstdint>

#define MAXN 100000
#define MAXE 1600000

// Scratch
__device__ __half g_h1h[MAXN * 128];   // x @ W1, fp16 (gather payload)
__device__ float  g_out1[MAXN * 128];  // relu(aggregate + b1), fp32
__device__ __half g_h2h[MAXN * 64];    // out1 @ W2, fp16 (gather payload)
__device__ float  g_dinv[MAXN];
__device__ int    g_deg[MAXN];
__device__ int    g_off[MAXN + 1];
__device__ int    g_cur[MAXN];
__device__ int    g_blk[256];
__device__ int    g_csr[MAXE];         // source node per CSR slot
__device__ float  g_csn[MAXE];         // dinv[source] per CSR slot
// Pre-split, pre-transposed weights: Bt[n][k] packed bf16 (hi and lo of residual)
__device__ __nv_bfloat16 g_w1h[128 * 128];
__device__ __nv_bfloat16 g_w1l[128 * 128];
__device__ __nv_bfloat16 g_w2h[64 * 128];
__device__ __nv_bfloat16 g_w2l[64 * 128];

// ---------------------------------------------------------------------------
// CSR construction
// ---------------------------------------------------------------------------
__global__ void k_hist(const int* __restrict__ dst, int E) {
    int i = blockIdx.x * blockDim.x + threadIdx.x;
    if (i < E) atomicAdd(&g_deg[dst[i]], 1);
}
// scan1: block-wise exclusive scan of degrees; ALSO computes dinv (fused).
__global__ void k_scan1(int n) {
    __shared__ int sh[1024];
    int t = threadIdx.x, i = blockIdx.x * 1024 + t;
    int v = (i < n) ? g_deg[i] : 0;
    if (i < n) g_dinv[i] = rsqrtf((float)(v + 1));
    sh[t] = v;
    __syncthreads();
    for (int o = 1; o < 1024; o <<= 1) {
        int x = (t >= o) ? sh[t - o] : 0;
        __syncthreads();
        sh[t] += x;
        __syncthreads();
    }
    if (i < n) g_off[i] = sh[t] - v;
    if (t == 1023) g_blk[blockIdx.x] = sh[t];
}
// scan3: fuses the block-total scan (formerly scan2) — each block redundantly
// scans the <=128 block totals in smem, then applies the prefix.
__global__ void k_scan3(int n, int E, int nb) {
    __shared__ int pr[128];
    int t = threadIdx.x;
    if (t < 128) pr[t] = (t < nb) ? g_blk[t] : 0;
    __syncthreads();
#pragma unroll
    for (int o = 1; o < 128; o <<= 1) {
        int x = (t >= o && t < 128) ? pr[t - o] : 0;
        __syncthreads();
        if (t < 128) pr[t] += x;
        __syncthreads();
    }
    // pr[] now inclusive; exclusive prefix for block b = pr[b] - blk[b]
    int i = blockIdx.x * blockDim.x + t;
    if (i < n) {
        int b = i >> 10;
        int ex = pr[b] - ((b < nb) ? g_blk[b] : 0);
        int o = g_off[i] + ex;
        g_off[i] = o;
        g_cur[i] = o;
    }
    if (i == 0) g_off[n] = E;
}
__global__ void k_fill(const int* __restrict__ src, const int* __restrict__ dst, int E) {
    int i = blockIdx.x * blockDim.x + threadIdx.x;
    if (i < E) {
        int s = src[i], d = dst[i];
        int pos = atomicAdd(&g_cur[d], 1);
        g_csr[pos] = s;
        g_csn[pos] = g_dinv[s];
    }
}

// ---------------------------------------------------------------------------
// Weight prep: split fp32 -> bf16 hi + bf16(residual), transposed Bt[n][k].
// ---------------------------------------------------------------------------
__global__ void k_prep_w(const float* __restrict__ W1, const float* __restrict__ W2) {
    int i = blockIdx.x * blockDim.x + threadIdx.x;
    if (i < 128 * 128) {
        int k = i >> 7, nn = i & 127;
        float v = W1[i];
        __nv_bfloat16 h = __float2bfloat16(v);
        __nv_bfloat16 l = __float2bfloat16(v - __bfloat162float(h));
        g_w1h[nn * 128 + k] = h;
        g_w1l[nn * 128 + k] = l;
    } else if (i < 128 * 128 + 128 * 64) {
        int j = i - 128 * 128;
        int k = j >> 6, nn = j & 63;
        float v = W2[j];
        __nv_bfloat16 h = __float2bfloat16(v);
        __nv_bfloat16 l = __float2bfloat16(v - __bfloat162float(h));
        g_w2h[nn * 128 + k] = h;
        g_w2l[nn * 128 + k] = l;
    }
}

// ---------------------------------------------------------------------------
// HMMA GEMM: C[n x NOUT] = A[n x 128] @ W[128 x NOUT]
// bf16 split 3-pass (AhBh + AhBl + AlBh), fp32 accum, fp16 output.
// ---------------------------------------------------------------------------
#define STRIDE_W 68   // words per row: 64 data + 4 pad -> conflict-free fragments

__device__ __forceinline__ void mma_bf16(float* c, const uint32_t* a, const uint32_t* b) {
    asm volatile(
        "mma.sync.aligned.m16n8k16.row.col.f32.bf16.bf16.f32 "
        "{%0,%1,%2,%3}, {%4,%5,%6,%7}, {%8,%9}, {%0,%1,%2,%3};"
        : "+f"(c[0]), "+f"(c[1]), "+f"(c[2]), "+f"(c[3])
        : "r"(a[0]), "r"(a[1]), "r"(a[2]), "r"(a[3]), "r"(b[0]), "r"(b[1]));
}

template <int NOUT>
__global__ void __launch_bounds__(256)
gemm_mma(const float* __restrict__ A, const __nv_bfloat16* __restrict__ Wh,
         const __nv_bfloat16* __restrict__ Wl, __half* __restrict__ C, int n) {
    extern __shared__ uint32_t sm[];
    uint32_t* ASH = sm;
    uint32_t* ASL = ASH + 128 * STRIDE_W;
    uint32_t* BSH = ASL + 128 * STRIDE_W;
    uint32_t* BSL = BSH + NOUT * STRIDE_W;

    const int t = threadIdx.x;
    const int wid = t >> 5, lane = t & 31;
    const int g = lane >> 2, tq = lane & 3;
    const int row0 = blockIdx.x * 128;

    for (int i = t; i < NOUT * 64; i += 256) {
        int r = i >> 6, w = i & 63;
        BSH[r * STRIDE_W + w] = ((const uint32_t*)Wh)[i];
        BSL[r * STRIDE_W + w] = ((const uint32_t*)Wl)[i];
    }
    for (int i = t; i < 128 * 64; i += 256) {
        int r = i >> 6, w = i & 63;
        int gr = row0 + r;
        float2 v = make_float2(0.f, 0.f);
        if (gr < n) v = ((const float2*)(A + (size_t)gr * 128))[w];
        __nv_bfloat16 hx = __float2bfloat16(v.x), hy = __float2bfloat16(v.y);
        __nv_bfloat16 lx = __float2bfloat16(v.x - __bfloat162float(hx));
        __nv_bfloat16 ly = __float2bfloat16(v.y - __bfloat162float(hy));
        uint32_t hw = ((uint32_t)__bfloat16_as_ushort(hy) << 16) | __bfloat16_as_ushort(hx);
        uint32_t lw = ((uint32_t)__bfloat16_as_ushort(ly) << 16) | __bfloat16_as_ushort(lx);
        ASH[r * STRIDE_W + w] = hw;
        ASL[r * STRIDE_W + w] = lw;
    }
    __syncthreads();

    constexpr int NT = NOUT / 8;
    float acc[NT][4];
#pragma unroll
    for (int i = 0; i < NT; i++)
#pragma unroll
        for (int j = 0; j < 4; j++) acc[i][j] = 0.f;

    const int wrow = wid * 16;

#pragma unroll
    for (int kk = 0; kk < 8; kk++) {
        uint32_t ah[4], al[4];
        int ra = (wrow + g) * STRIDE_W + kk * 8 + tq;
        int rb = (wrow + g + 8) * STRIDE_W + kk * 8 + tq;
        ah[0] = ASH[ra];     ah[1] = ASH[rb];
        ah[2] = ASH[ra + 4]; ah[3] = ASH[rb + 4];
        al[0] = ASL[ra];     al[1] = ASL[rb];
        al[2] = ASL[ra + 4]; al[3] = ASL[rb + 4];

#pragma unroll
        for (int nt = 0; nt < NT; nt++) {
            int nb = (nt * 8 + g) * STRIDE_W + kk * 8 + tq;
            uint32_t bh[2], bl[2];
            bh[0] = BSH[nb]; bh[1] = BSH[nb + 4];
            bl[0] = BSL[nb]; bl[1] = BSL[nb + 4];
            mma_bf16(acc[nt], ah, bh);
            mma_bf16(acc[nt], ah, bl);
            mma_bf16(acc[nt], al, bh);
        }
    }

    int gr0 = row0 + wrow + g;
    int gr1 = gr0 + 8;
#pragma unroll
    for (int nt = 0; nt < NT; nt++) {
        int col = nt * 8 + tq * 2;
        if (gr0 < n)
            *(__half2*)(C + (size_t)gr0 * NOUT + col) = __floats2half2_rn(acc[nt][0], acc[nt][1]);
        if (gr1 < n)
            *(__half2*)(C + (size_t)gr1 * NOUT + col) = __floats2half2_rn(acc[nt][2], acc[nt][3]);
    }
}

// ---------------------------------------------------------------------------
// Layer-1 gather: warp per destination node, 128 fp16 feats (lane = 4),
// fp32 accumulate, 4-wide edge unroll. Node range [start, start+count).
// ---------------------------------------------------------------------------
__device__ __forceinline__ float4 ld_h4(const __half* base, int lane) {
    uint2 raw = ((const uint2*)base)[lane];
    float2 a = __half22float2(*(__half2*)&raw.x);
    float2 b = __half22float2(*(__half2*)&raw.y);
    return make_float4(a.x, a.y, b.x, b.y);
}

__global__ void k_gather128(const __half* __restrict__ h, const float* __restrict__ b1,
                            float* __restrict__ out, int start, int count, int n) {
    int node = start + blockIdx.x * 8 + (threadIdx.x >> 5);
    int lane = threadIdx.x & 31;
    if (node >= start + count || node >= n) return;

    float dd = g_dinv[node];
    float self = dd * dd;
    float4 sv = ld_h4(h + (size_t)node * 128, lane);
    float4 acc0 = make_float4(sv.x * self, sv.y * self, sv.z * self, sv.w * self);
    float4 acc1 = make_float4(0.f, 0.f, 0.f, 0.f);

    int e = g_off[node];
    const int end = g_off[node + 1];

    for (; e + 3 < end; e += 4) {
        int s0 = g_csr[e],     s1 = g_csr[e + 1];
        int s2 = g_csr[e + 2], s3 = g_csr[e + 3];
        float w0 = g_csn[e] * dd,     w1 = g_csn[e + 1] * dd;
        float w2 = g_csn[e + 2] * dd, w3 = g_csn[e + 3] * dd;
        float4 v0 = ld_h4(h + (size_t)s0 * 128, lane);
        float4 v1 = ld_h4(h + (size_t)s1 * 128, lane);
        float4 v2 = ld_h4(h + (size_t)s2 * 128, lane);
        float4 v3 = ld_h4(h + (size_t)s3 * 128, lane);
        acc0.x += v0.x * w0; acc0.y += v0.y * w0; acc0.z += v0.z * w0; acc0.w += v0.w * w0;
        acc1.x += v1.x * w1; acc1.y += v1.y * w1; acc1.z += v1.z * w1; acc1.w += v1.w * w1;
        acc0.x += v2.x * w2; acc0.y += v2.y * w2; acc0.z += v2.z * w2; acc0.w += v2.w * w2;
        acc1.x += v3.x * w3; acc1.y += v3.y * w3; acc1.z += v3.z * w3; acc1.w += v3.w * w3;
    }
    for (; e < end; ++e) {
        int s = g_csr[e];
        float w = g_csn[e] * dd;
        float4 v = ld_h4(h + (size_t)s * 128, lane);
        acc0.x += v.x * w; acc0.y += v.y * w; acc0.z += v.z * w; acc0.w += v.w * w;
    }

    float4 bb = ((const float4*)b1)[lane];
    acc0.x = fmaxf(acc0.x + acc1.x + bb.x, 0.f);
    acc0.y = fmaxf(acc0.y + acc1.y + bb.y, 0.f);
    acc0.z = fmaxf(acc0.z + acc1.z + bb.z, 0.f);
    acc0.w = fmaxf(acc0.w + acc1.w + bb.w, 0.f);
    ((float4*)(out + (size_t)node * 128))[lane] = acc0;
}

// ---------------------------------------------------------------------------
// Layer-2 gather + bias + log_softmax: half-warp per node, 64 fp16 feats.
// ---------------------------------------------------------------------------
__global__ void k_gather64_lsm(const __half* __restrict__ h, const float* __restrict__ b2,
                               float* __restrict__ out, int n) {
    int node = blockIdx.x * 16 + (threadIdx.x >> 4);
    int lane = threadIdx.x & 15;
    if (node >= n) return;

    float dd = g_dinv[node];
    float self = dd * dd;
    float4 sv = ld_h4(h + (size_t)node * 64, lane);
    float4 acc0 = make_float4(sv.x * self, sv.y * self, sv.z * self, sv.w * self);
    float4 acc1 = make_float4(0.f, 0.f, 0.f, 0.f);

    int e = g_off[node];
    const int end = g_off[node + 1];

    for (; e + 3 < end; e += 4) {
        int s0 = g_csr[e],     s1 = g_csr[e + 1];
        int s2 = g_csr[e + 2], s3 = g_csr[e + 3];
        float w0 = g_csn[e] * dd,     w1 = g_csn[e + 1] * dd;
        float w2 = g_csn[e + 2] * dd, w3 = g_csn[e + 3] * dd;
        float4 v0 = ld_h4(h + (size_t)s0 * 64, lane);
        float4 v1 = ld_h4(h + (size_t)s1 * 64, lane);
        float4 v2 = ld_h4(h + (size_t)s2 * 64, lane);
        float4 v3 = ld_h4(h + (size_t)s3 * 64, lane);
        acc0.x += v0.x * w0; acc0.y += v0.y * w0; acc0.z += v0.z * w0; acc0.w += v0.w * w0;
        acc1.x += v1.x * w1; acc1.y += v1.y * w1; acc1.z += v1.z * w1; acc1.w += v1.w * w1;
        acc0.x += v2.x * w2; acc0.y += v2.y * w2; acc0.z += v2.z * w2; acc0.w += v2.w * w2;
        acc1.x += v3.x * w3; acc1.y += v3.y * w3; acc1.z += v3.z * w3; acc1.w += v3.w * w3;
    }
    for (; e < end; ++e) {
        int s = g_csr[e];
        float w = g_csn[e] * dd;
        float4 v = ld_h4(h + (size_t)s * 64, lane);
        acc0.x += v.x * w; acc0.y += v.y * w; acc0.z += v.z * w; acc0.w += v.w * w;
    }

    float4 bb = ((const float4*)b2)[lane];
    acc0.x += acc1.x + bb.x; acc0.y += acc1.y + bb.y;
    acc0.z += acc1.z + bb.z; acc0.w += acc1.w + bb.w;

    float m = fmaxf(fmaxf(acc0.x, acc0.y), fmaxf(acc0.z, acc0.w));
#pragma unroll
    for (int o = 8; o; o >>= 1) m = fmaxf(m, __shfl_xor_sync(0xFFFFFFFFu, m, o));
    float sum = __expf(acc0.x - m) + __expf(acc0.y - m) + __expf(acc0.z - m) + __expf(acc0.w - m);
#pragma unroll
    for (int o = 8; o; o >>= 1) sum += __shfl_xor_sync(0xFFFFFFFFu, sum, o);
    float lse = __logf(sum) + m;

    ((float4*)(out + (size_t)node * 64))[lane] =
        make_float4(acc0.x - lse, acc0.y - lse, acc0.z - lse, acc0.w - lse);
}

// ---------------------------------------------------------------------------
extern "C" void kernel_launch(void* const* d_in, const int* in_sizes, int n_in,
                              void* d_out, int out_size) {
    const float* x  = (const float*)d_in[0];
    const float* W1 = (const float*)d_in[1];
    const float* b1 = (const float*)d_in[2];
    const float* W2 = (const float*)d_in[3];
    const float* b2 = (const float*)d_in[4];
    const int*   ei = (const int*)d_in[5];

    const int n = in_sizes[0] / 128;
    const int E = in_sizes[5] / 2;
    const int* src = ei;
    const int* dst = ei + E;
    float* out = (float*)d_out;

    __half* h1h  = nullptr; cudaGetSymbolAddress((void**)&h1h, g_h1h);
    float*  out1 = nullptr; cudaGetSymbolAddress((void**)&out1, g_out1);
    __half* h2h  = nullptr; cudaGetSymbolAddress((void**)&h2h, g_h2h);
    int*    degp = nullptr; cudaGetSymbolAddress((void**)&degp, g_deg);
    __nv_bfloat16 *w1h, *w1l, *w2h, *w2l;
    cudaGetSymbolAddress((void**)&w1h, g_w1h);
    cudaGetSymbolAddress((void**)&w1l, g_w1l);
    cudaGetSymbolAddress((void**)&w2h, g_w2h);
    cudaGetSymbolAddress((void**)&w2l, g_w2l);

    const int T = 256;
    const int nb = (n + 1023) / 1024;

    constexpr int SM1 = (2 * 128 * STRIDE_W + 2 * 128 * STRIDE_W) * 4;
    constexpr int SM2 = (2 * 128 * STRIDE_W + 2 * 64 * STRIDE_W) * 4;
    cudaFuncSetAttribute(gemm_mma<128>, cudaFuncAttributeMaxDynamicSharedMemorySize, SM1);
    cudaFuncSetAttribute(gemm_mma<64>,  cudaFuncAttributeMaxDynamicSharedMemorySize, SM2);

    // One-time stream/event creation (host-side resources only)
    static cudaStream_t s2 = nullptr;
    static cudaEvent_t evFork = nullptr, evJoin = nullptr, evGA = nullptr, evG2 = nullptr;
    if (!s2) {
        cudaStreamCreateWithFlags(&s2, cudaStreamNonBlocking);
        cudaEventCreateWithFlags(&evFork, cudaEventDisableTiming);
        cudaEventCreateWithFlags(&evJoin, cudaEventDisableTiming);
        cudaEventCreateWithFlags(&evGA, cudaEventDisableTiming);
        cudaEventCreateWithFlags(&evG2, cudaEventDisableTiming);
    }

    // Fork: GEMM1 path (prep_w -> gemm1) runs on s2, concurrent with CSR build
    cudaEventRecord(evFork, 0);
    cudaStreamWaitEvent(s2, evFork, 0);

    // s2: weight prep + layer-1 GEMM (depends only on x, W1, W2)
    k_prep_w<<<(128 * 128 + 128 * 64 + T - 1) / T, T, 0, s2>>>(W1, W2);
    const int gb = (n + 127) / 128;
    gemm_mma<128><<<gb, T, SM1, s2>>>(x, w1h, w1l, h1h, n);
    cudaEventRecord(evJoin, s2);

    // main stream: CSR build (dinv fused into scan1; scan2 fused into scan3)
    cudaMemsetAsync(degp, 0, n * sizeof(int));
    k_hist<<<(E + T - 1) / T, T>>>(dst, E);
    k_scan1<<<nb, 1024>>>(n);
    k_scan3<<<(n + T - 1) / T, T>>>(n, E, nb);
    k_fill<<<(E + T - 1) / T, T>>>(src, dst, E);

    // Join: gather needs both CSR and gemm1 output
    cudaStreamWaitEvent(0, evJoin, 0);

    // Chunked overlap: gather128 chunk A -> (gemm2 chunk A on s2) || gather128 chunk B
    const int nA = ((n / 2 + 127) / 128) * 128;   // chunk A node count (row-tile aligned)
    const int nB = n - nA;

    k_gather128<<<(nA + 7) / 8, T>>>(h1h, b1, out1, 0, nA, n);
    cudaEventRecord(evGA, 0);

    // s2: gemm2 on rows [0, nA) while main does gather128 on [nA, n)
    cudaStreamWaitEvent(s2, evGA, 0);
    gemm_mma<64><<<nA / 128, T, SM2, s2>>>(out1, w2h, w2l, h2h, nA);
    cudaEventRecord(evG2, s2);

    k_gather128<<<(nB + 7) / 8, T>>>(h1h, b1, out1, nA, nB, n);

    // main: gemm2 on rows [nA, n) (depends on chunk B, same stream)
    gemm_mma<64><<<(nB + 127) / 128, T, SM2>>>(out1 + (size_t)nA * 128, w2h, w2l,
                                               h2h + (size_t)nA * 64, nB);

    // gather64 needs ALL of h2 (both chunks)
    cudaStreamWaitEvent(0, evG2, 0);
    k_gather64_lsm<<<(n + 15) / 16, T>>>(h2h, b2, out, n);
}